// round 14
// baseline (speedup 1.0000x reference)
#include <cuda_runtime.h>
#include <cuda_bf16.h>
#include <math.h>

#define NN 100000
#define NE 1200000
#define NC 64
#define NG 256
#define EPSBN 1e-5f
#define LOG2E 1.44269504f
#define HALF_LN2 0.34657359f

#define EWARPS 16384
#define ECHUNK ((NE + EWARPS - 1) / EWARPS)

// ---------------- static scratch ----------------
__device__ float         d_h[NN * NC];
__device__ float         d_y[NN * NC];
__device__ float         d_A[NN * 2 * NC];   // interleaved u64 pairs: (0.5*(f+bf), log2e*(s+bs)) per channel
__device__ unsigned int  d_Bb[NN * NC];      // bf16x2: hi = 0.5*f, lo = log2e*s
__device__ int           d_cnt[NN];
__device__ int           d_fill[NN];
__device__ int           d_off[NN + 1];
__device__ int2          d_edge[NE];         // (src, ea bits) sorted by dst
__device__ int           d_wstart[EWARPS];   // first node of each warp chunk (-1 = empty warp)
__device__ float         d_statsf[2 * NC];   // fp32 BN sums: [c]=sum, [64+c]=sumsq
__device__ float         d_bnscale[NC];
__device__ float         d_bnshift[NC];
__device__ float         d_pool[NG * NC];
__device__ int           d_gcnt[NG];

// ---------------- helpers ----------------
__device__ __forceinline__ unsigned long long pack2(float x, float y) {
    unsigned long long r;
    asm("mov.b64 %0, {%1, %2};" : "=l"(r) : "f"(x), "f"(y));
    return r;
}
__device__ __forceinline__ void unpack2(unsigned long long v, float& x, float& y) {
    asm("mov.b64 {%0, %1}, %2;" : "=f"(x), "=f"(y) : "l"(v));
}
__device__ __forceinline__ unsigned long long ffma2(unsigned long long a,
                                                    unsigned long long b,
                                                    unsigned long long c) {
    unsigned long long d;
    asm("fma.rn.f32x2 %0, %1, %2, %3;" : "=l"(d) : "l"(a), "l"(b), "l"(c));
    return d;
}
__device__ __forceinline__ unsigned long long fadd2(unsigned long long a,
                                                    unsigned long long b) {
    unsigned long long d;
    asm("add.rn.f32x2 %0, %1, %2;" : "=l"(d) : "l"(a), "l"(b));
    return d;
}
__device__ __forceinline__ float tanh_f(float x) {
    float t;
    asm("tanh.approx.f32 %0, %1;" : "=f"(t) : "f"(x));
    return t;
}
__device__ __forceinline__ float ex2_f(float x) {
    float t;
    asm("ex2.approx.ftz.f32 %0, %1;" : "=f"(t) : "f"(x));
    return t;
}
__device__ __forceinline__ float lg2_f(float x) {
    float t;
    asm("lg2.approx.f32 %0, %1;" : "=f"(t) : "f"(x));
    return t;
}
__device__ __forceinline__ unsigned int packfs(float fhalf, float slog) {
    __nv_bfloat162 h2 = __floats2bfloat162_rn(slog, fhalf);  // .x low = s, .y high = f
    return *reinterpret_cast<unsigned int*>(&h2);
}
__device__ __forceinline__ unsigned long long expandfs(unsigned int w) {
    return pack2(__int_as_float(w & 0xffff0000u), __int_as_float(w << 16));
}

// ---------------- init ----------------
__global__ void init_kernel() {
    int i = blockIdx.x * blockDim.x + threadIdx.x;
    if (i < NN) { d_cnt[i] = 0; d_fill[i] = 0; }
    if (i < NG * NC) d_pool[i] = 0.f;
    if (i < NG) d_gcnt[i] = 0;
    if (i < 2 * NC) d_statsf[i] = 0.f;
}

__global__ void hist_kernel(const int* __restrict__ ei, const int* __restrict__ batch) {
    int e = blockIdx.x * blockDim.x + threadIdx.x;
    if (e < NE) atomicAdd(&d_cnt[ei[NE + e]], 1);
    if (e < NN) atomicAdd(&d_gcnt[batch[e]], 1);
}

__global__ void scan_kernel() {
    const int CH = (NN + 1023) / 1024;
    int tid = threadIdx.x;
    int start = tid * CH;
    int end = min(start + CH, NN);
    int s = 0;
    for (int i = start; i < end; i++) s += d_cnt[i];

    __shared__ int warp_sums[32];
    int lane = tid & 31, w = tid >> 5;
    int incl = s;
    #pragma unroll
    for (int o = 1; o < 32; o <<= 1) {
        int t = __shfl_up_sync(0xffffffffu, incl, o);
        if (lane >= o) incl += t;
    }
    if (lane == 31) warp_sums[w] = incl;
    __syncthreads();
    if (w == 0) {
        int v = warp_sums[lane];
        #pragma unroll
        for (int o = 1; o < 32; o <<= 1) {
            int t = __shfl_up_sync(0xffffffffu, v, o);
            if (lane >= o) v += t;
        }
        warp_sums[lane] = v;
    }
    __syncthreads();
    int excl = incl - s + (w > 0 ? warp_sums[w - 1] : 0);
    int run = excl;
    for (int i = start; i < end; i++) { d_off[i] = run; run += d_cnt[i]; }
    if (tid == 1023) d_off[NN] = NE;
}

__global__ void scatter_kernel(const int* __restrict__ ei, const float* __restrict__ ea) {
    int e = blockIdx.x * blockDim.x + threadIdx.x;
    if (e < NE) {
        int d = ei[NE + e];
        int p = atomicAdd(&d_fill[d], 1);
        d_edge[d_off[d] + p] = make_int2(ei[e], __float_as_int(ea[e]));
    }
}

// ---------------- per-warp start node: binary search d_off ----------------
__global__ void wstart_kernel() {
    int w = blockIdx.x * 256 + threadIdx.x;
    if (w >= EWARPS) return;
    int e = w * ECHUNK;
    if (e >= NE) { d_wstart[w] = -1; return; }
    int lo = 0, hi = NN;
    while (hi - lo > 1) {
        int mid = (lo + hi) >> 1;
        if (d_off[mid] <= e) lo = mid; else hi = mid;
    }
    d_wstart[w] = lo;
}

// ---------------- BN prep (fp32 stats; zeroes them) ----------------
__global__ void bn_prep_kernel(const float* __restrict__ g, const float* __restrict__ beta) {
    int c = threadIdx.x;
    if (c < NC) {
        float mu = d_statsf[c] * (1.f / (float)NN);
        float var = d_statsf[NC + c] * (1.f / (float)NN) - mu * mu;
        float rs = rsqrtf(var + EPSBN);
        float sc = g[c] * rs;
        d_bnscale[c] = sc;
        d_bnshift[c] = beta[c] - mu * sc;
        d_statsf[c] = 0.f;
        d_statsf[NC + c] = 0.f;
    }
}

// ---------------- input layer ----------------
__global__ __launch_bounds__(256) void input_kernel(const float* __restrict__ x,
                                                    const float* __restrict__ W,
                                                    const float* __restrict__ b) {
    __shared__ float ws[12 * 64];
    __shared__ float xs[64 * 12];
    __shared__ float ssum[64], ssq[64];
    int tid = threadIdx.x;
    int base = blockIdx.x * 64;
    for (int i = tid; i < 12 * 64; i += 256) ws[i] = W[i];
    for (int i = tid; i < 64 * 12; i += 256) {
        int n = i / 12;
        xs[i] = (base + n < NN) ? x[(size_t)(base + n) * 12 + (i % 12)] : 0.f;
    }
    if (tid < 64) { ssum[tid] = 0.f; ssq[tid] = 0.f; }
    __syncthreads();
    int c = tid & 63;
    float bc = b[c];
    float lsum = 0.f, lsq = 0.f;
    #pragma unroll
    for (int p = 0; p < 16; p++) {
        int n = p * 4 + (tid >> 6);
        float acc = bc;
        #pragma unroll
        for (int k = 0; k < 12; k++) acc = fmaf(xs[n * 12 + k], ws[k * 64 + c], acc);
        if (base + n < NN) {
            d_y[(size_t)(base + n) * 64 + c] = acc;
            lsum += acc;
            lsq = fmaf(acc, acc, lsq);
        }
    }
    atomicAdd(&ssum[c], lsum);
    atomicAdd(&ssq[c], lsq);
    __syncthreads();
    if (tid < 64) {
        atomicAdd(&d_statsf[tid], ssum[tid]);
        atomicAdd(&d_statsf[64 + tid], ssq[tid]);
    }
}

// ---------------- unified GEMM: BN(prev)+res+relu fused, all 4 quadrants ----------------
extern __shared__ float smem_g[];
__global__ __launch_bounds__(256) void gemm_kernel(const float* __restrict__ Wf,
                                                   const float* __restrict__ Ws,
                                                   const float* __restrict__ bfv,
                                                   const float* __restrict__ bsv,
                                                   int residual) {
    float* hsT = smem_g;                                                 // [64][65]
    unsigned long long* wsm2 = (unsigned long long*)(smem_g + 64 * 65);  // [64][128]
    __shared__ float sbn[128];
    int tid = threadIdx.x;
    int nb = blockIdx.x * 64;

    if (tid < 64) { sbn[tid] = d_bnscale[tid]; sbn[64 + tid] = d_bnshift[tid]; }
    __syncthreads();

    #pragma unroll
    for (int m = 0; m < 32; m++) {
        int lin = m * 256 + tid;
        int k = lin >> 7, ch = lin & 127;
        int row = ((ch >> 6) << 6) + k;
        int c = ch & 63;
        wsm2[lin] = pack2(Wf[row * 64 + c], Ws[row * 64 + c]);
    }
    #pragma unroll
    for (int m = 0; m < 16; m++) {
        int lin = m * 256 + tid;
        int a = lin >> 6, c = lin & 63;
        int n = nb + a;
        float v = 0.f;
        if (n < NN) {
            size_t g = (size_t)n * 64 + c;
            v = fmaf(d_y[g], sbn[c], sbn[64 + c]);
            if (residual) v += d_h[g];
            v = fmaxf(v, 0.f);
            d_h[g] = v;
            d_y[g] = 0.f;
        }
        hsT[c * 65 + a] = v;
    }
    __syncthreads();

    int ty = tid >> 5, tx = tid & 31;
    int chbase = ((tx & 15) << 2) + ((tx >> 4) << 6);
    unsigned long long acc[8][4];
    #pragma unroll
    for (int j = 0; j < 8; j++)
        #pragma unroll
        for (int q = 0; q < 4; q++) acc[j][q] = 0ull;

    #pragma unroll 4
    for (int k = 0; k < 64; k++) {
        const unsigned long long* wr = &wsm2[k * 128 + chbase];
        ulonglong2 bq0 = *(const ulonglong2*)(wr);
        ulonglong2 bq1 = *(const ulonglong2*)(wr + 2);
        const float* hr = &hsT[k * 65 + ty * 8];
        #pragma unroll
        for (int j = 0; j < 8; j++) {
            float a = hr[j];
            unsigned long long aa = pack2(a, a);
            acc[j][0] = ffma2(aa, bq0.x, acc[j][0]);
            acc[j][1] = ffma2(aa, bq0.y, acc[j][1]);
            acc[j][2] = ffma2(aa, bq1.x, acc[j][2]);
            acc[j][3] = ffma2(aa, bq1.y, acc[j][3]);
        }
    }

    bool aSide = (tx < 16);
    int ch0 = (tx & 15) * 4;
    float bfr[4], bsr[4];
    if (aSide) {
        #pragma unroll
        for (int q = 0; q < 4; q++) {
            bfr[q] = 0.5f * bfv[ch0 + q];          // pre-halved for tanh fold
            bsr[q] = LOG2E * bsv[ch0 + q];
        }
    }
    unsigned long long* A2 = (unsigned long long*)d_A;
    #pragma unroll
    for (int j = 0; j < 8; j++) {
        int n = nb + ty * 8 + j;
        if (n >= NN) continue;
        #pragma unroll
        for (int q = 0; q < 4; q++) {
            float f, s;
            unpack2(acc[j][q], f, s);
            if (aSide) {
                float fa = fmaf(0.5f, f, bfr[q]);
                float sa = fmaf(LOG2E, s, bsr[q]);
                A2[(size_t)n * 64 + ch0 + q] = pack2(fa, sa);
            } else {
                d_Bb[(size_t)n * 64 + ch0 + q] = packfs(0.5f * f, LOG2E * s);
            }
        }
    }
}

// ---------------- edge pass: warp-chunk CSR walk, prefetch + flush-path stats ----------------
__global__ __launch_bounds__(128) void edge_kernel(const float* __restrict__ Wf,
                                                   const float* __restrict__ Ws) {
    int lane = threadIdx.x & 31;
    int gw = blockIdx.x * 4 + (threadIdx.x >> 5);
    int e = gw * ECHUNK;
    int e1 = min(e + ECHUNK, NE);
    if (e >= e1) return;
    int c0 = lane, c1 = lane + 32;
    unsigned long long wfs0 = pack2(0.5f * Wf[128 * 64 + c0], LOG2E * Ws[128 * 64 + c0]);
    unsigned long long wfs1 = pack2(0.5f * Wf[128 * 64 + c1], LOG2E * Ws[128 * 64 + c1]);

    int cur = d_wstart[gw];
    const int sharedFirst = cur;
    const int nextStart = (gw + 1 < EWARPS) ? d_wstart[gw + 1] : -1;
    int nend = d_off[cur + 1];                 // > e by construction

    const unsigned long long* A2 = (const unsigned long long*)d_A;
    unsigned long long afs0 = A2[(size_t)cur * 64 + c0];
    unsigned long long afs1 = A2[(size_t)cur * 64 + c1];

    // pipeline state: current edge (record + B data), next edge record
    int2 m_cur = d_edge[e];
    unsigned int w0_cur = d_Bb[(size_t)m_cur.x * 64 + c0];
    unsigned int w1_cur = d_Bb[(size_t)m_cur.x * 64 + c1];
    int2 m_nxt = d_edge[min(e + 1, e1 - 1)];

    unsigned long long acc0 = 0ull, acc1 = 0ull;   // (sum t*l, sum l)
    float ls0 = 0.f, lq0 = 0.f, ls1 = 0.f, lq1 = 0.f;

    while (true) {
        // prefetch: record for e+2 (independent), B-gather for e+1 (record ready)
        int2 m_n2 = d_edge[min(e + 2, e1 - 1)];
        unsigned int w0_n = d_Bb[(size_t)m_nxt.x * 64 + c0];
        unsigned int w1_n = d_Bb[(size_t)m_nxt.x * 64 + c1];

        // compute on current edge
        float ea = __int_as_float(m_cur.y);
        unsigned long long ea2 = pack2(ea, ea);
        unsigned long long t0p = fadd2(ffma2(ea2, wfs0, afs0), expandfs(w0_cur));
        float tf0, ts0; unpack2(t0p, tf0, ts0);
        float th0 = tanh_f(tf0);
        float l0 = lg2_f(1.f + ex2_f(ts0));
        acc0 = ffma2(pack2(th0, 1.f), pack2(l0, l0), acc0);

        unsigned long long t1p = fadd2(ffma2(ea2, wfs1, afs1), expandfs(w1_cur));
        float tf1, ts1; unpack2(t1p, tf1, ts1);
        float th1 = tanh_f(tf1);
        float l1 = lg2_f(1.f + ex2_f(ts1));
        acc1 = ffma2(pack2(th1, 1.f), pack2(l1, l1), acc1);

        e++;
        if (e == nend || e == e1) {
            float aT0, aL0, aT1, aL1;
            unpack2(acc0, aT0, aL0);
            unpack2(acc1, aT1, aL1);
            float v0 = HALF_LN2 * (aT0 + aL0);
            float v1 = HALF_LN2 * (aT1 + aL1);
            if (cur == sharedFirst || cur == nextStart) {
                // possibly shared with another warp: atomic; fixup counts stats
                atomicAdd(&d_y[(size_t)cur * 64 + c0], v0);
                atomicAdd(&d_y[(size_t)cur * 64 + c1], v1);
            } else {
                // wholly owned: plain store; count stats locally
                d_y[(size_t)cur * 64 + c0] = v0;
                d_y[(size_t)cur * 64 + c1] = v1;
                ls0 += v0; lq0 = fmaf(v0, v0, lq0);
                ls1 += v1; lq1 = fmaf(v1, v1, lq1);
            }
            if (e == e1) break;
            acc0 = 0ull; acc1 = 0ull;
            do { cur++; nend = d_off[cur + 1]; } while (nend <= e);
            afs0 = A2[(size_t)cur * 64 + c0];
            afs1 = A2[(size_t)cur * 64 + c1];
        }
        m_cur = m_nxt; w0_cur = w0_n; w1_cur = w1_n; m_nxt = m_n2;
    }
    atomicAdd(&d_statsf[c0], ls0);
    atomicAdd(&d_statsf[64 + c0], lq0);
    atomicAdd(&d_statsf[c1], ls1);
    atomicAdd(&d_statsf[64 + c1], lq1);
}

// ---------------- fixup: stats for shared (wstart) rows, deduped ----------------
__global__ __launch_bounds__(256) void fixup_kernel() {
    int lane = threadIdx.x & 31;
    int wid = (blockIdx.x * 256 + threadIdx.x) >> 5;
    int nw = gridDim.x * 8;
    float ls0 = 0.f, lq0 = 0.f, ls1 = 0.f, lq1 = 0.f;
    for (int w = wid; w < EWARPS; w += nw) {
        int n = d_wstart[w];
        if (n < 0) continue;
        if (w > 0 && d_wstart[w - 1] == n) continue;
        float v0 = d_y[(size_t)n * 64 + lane];
        float v1 = d_y[(size_t)n * 64 + 32 + lane];
        ls0 += v0; lq0 = fmaf(v0, v0, lq0);
        ls1 += v1; lq1 = fmaf(v1, v1, lq1);
    }
    atomicAdd(&d_statsf[lane], ls0);
    atomicAdd(&d_statsf[64 + lane], lq0);
    atomicAdd(&d_statsf[lane + 32], ls1);
    atomicAdd(&d_statsf[96 + lane], lq1);
}

// ---------------- BN apply + pooled (last layer, batch sorted) ----------------
__global__ __launch_bounds__(1024) void bn_pool_kernel(const int* __restrict__ batch) {
    __shared__ float psum[64];
    __shared__ int sg[2];
    int tid = threadIdx.x;
    int idx = blockIdx.x * 1024 + tid;
    int node = idx >> 6;
    int c = idx & 63;
    float v = fmaf(d_y[idx], d_bnscale[c], d_bnshift[c]) + d_h[idx];
    int g = batch[node];
    if (tid == 0)    sg[0] = g;
    if (tid == 1023) sg[1] = g;
    __syncthreads();
    int g0 = sg[0], g1 = sg[1];
    for (int gg = g0; gg <= g1; gg++) {
        if (tid < 64) psum[tid] = 0.f;
        __syncthreads();
        if (g == gg) atomicAdd(&psum[c], v);
        __syncthreads();
        if (tid < 64 && psum[tid] != 0.f) atomicAdd(&d_pool[gg * 64 + tid], psum[tid]);
        __syncthreads();
    }
}

// ---------------- final MLP ----------------
__global__ void mlp_kernel(const float* __restrict__ W1, const float* __restrict__ b1,
                           const float* __restrict__ W2, const float* __restrict__ b2,
                           float* __restrict__ out) {
    __shared__ float p[64];
    __shared__ float h1[32];
    int g = blockIdx.x;
    int tid = threadIdx.x;
    float inv = 1.f / fmaxf((float)d_gcnt[g], 1.f);
    p[tid] = d_pool[g * 64 + tid] * inv;
    __syncthreads();
    if (tid < 32) {
        float a = b1[tid];
        #pragma unroll
        for (int k = 0; k < 64; k++) a = fmaf(p[k], W1[k * 32 + tid], a);
        h1[tid] = fmaxf(a, 0.f);
    }
    __syncthreads();
    if (tid < 32) {
        float v = h1[tid] * W2[tid];
        #pragma unroll
        for (int o = 16; o > 0; o >>= 1) v += __shfl_down_sync(0xffffffffu, v, o);
        if (tid == 0) out[g] = v + b2[0];
    }
}

// ---------------- launcher ----------------
extern "C" void kernel_launch(void* const* d_in, const int* in_sizes, int n_in,
                              void* d_out, int out_size) {
    const float* x     = (const float*)d_in[0];
    const int*   ei    = (const int*)d_in[1];
    const float* ea    = (const float*)d_in[2];
    const int*   batch = (const int*)d_in[3];
    const float* W_in  = (const float*)d_in[4];
    const float* b_in  = (const float*)d_in[5];
    const float* g0    = (const float*)d_in[6];
    const float* beta0 = (const float*)d_in[7];
    const float* Wf[3] = {(const float*)d_in[8],  (const float*)d_in[14], (const float*)d_in[20]};
    const float* bf[3] = {(const float*)d_in[9],  (const float*)d_in[15], (const float*)d_in[21]};
    const float* Ws[3] = {(const float*)d_in[10], (const float*)d_in[16], (const float*)d_in[22]};
    const float* bs[3] = {(const float*)d_in[11], (const float*)d_in[17], (const float*)d_in[23]};
    const float* gg[3] = {(const float*)d_in[12], (const float*)d_in[18], (const float*)d_in[24]};
    const float* bb[3] = {(const float*)d_in[13], (const float*)d_in[19], (const float*)d_in[25]};
    const float* W1 = (const float*)d_in[26];
    const float* b1 = (const float*)d_in[27];
    const float* W2 = (const float*)d_in[28];
    const float* b2 = (const float*)d_in[29];
    float* out = (float*)d_out;

    const int GEMM_SMEM = 64 * 65 * 4 + 64 * 128 * 8;   // 82176 bytes
    cudaFuncSetAttribute(gemm_kernel, cudaFuncAttributeMaxDynamicSharedMemorySize, GEMM_SMEM);

    init_kernel<<<(NN + 255) / 256, 256>>>();
    hist_kernel<<<(NE + 255) / 256, 256>>>(ei, batch);
    scan_kernel<<<1, 1024>>>();
    scatter_kernel<<<(NE + 255) / 256, 256>>>(ei, ea);
    wstart_kernel<<<(EWARPS + 255) / 256, 256>>>();

    input_kernel<<<(NN + 63) / 64, 256>>>(x, W_in, b_in);
    bn_prep_kernel<<<1, 64>>>(g0, beta0);

    for (int l = 0; l < 3; l++) {
        gemm_kernel<<<(NN + 63) / 64, 256, GEMM_SMEM>>>(Wf[l], Ws[l], bf[l], bs[l],
                                                        (l == 0) ? 0 : 1);
        edge_kernel<<<EWARPS / 4, 128>>>(Wf[l], Ws[l]);
        fixup_kernel<<<64, 256>>>();
        bn_prep_kernel<<<1, 64>>>(gg[l], bb[l]);
    }

    bn_pool_kernel<<<(NN * NC + 1023) / 1024, 1024>>>(batch);
    mlp_kernel<<<NG, 64>>>(W1, b1, W2, b2, out);
}

// round 15
// speedup vs baseline: 1.1578x; 1.1578x over previous
#include <cuda_runtime.h>
#include <cuda_bf16.h>
#include <math.h>

#define NN 100000
#define NE 1200000
#define NC 64
#define NG 256
#define EPSBN 1e-5f
#define LOG2E 1.44269504f
#define HALF_LN2 0.34657359f

#define EWARPS 16384
#define ECHUNK ((NE + EWARPS - 1) / EWARPS)
#define SBLOCKS 224

// ---------------- static scratch ----------------
__device__ float         d_h[NN * NC];
__device__ float         d_y[NN * NC];
__device__ float         d_A[NN * 2 * NC];   // interleaved u64 pairs: (0.5*(f+bf), log2e*(s+bs)) per channel
__device__ unsigned int  d_Bb[NN * NC];      // bf16x2: hi = 0.5*f, lo = log2e*s
__device__ int           d_cnt[NN];
__device__ int           d_fill[NN];
__device__ int           d_off[NN + 1];
__device__ int2          d_edge[NE];         // (src, ea bits) sorted by dst
__device__ int           d_wstart[EWARPS];   // first node of each warp chunk
__device__ double        d_stats[2 * NC];
__device__ float         d_bnscale[NC];
__device__ float         d_bnshift[NC];
__device__ float         d_pool[NG * NC];
__device__ int           d_gcnt[NG];

// ---------------- helpers ----------------
__device__ __forceinline__ unsigned long long pack2(float x, float y) {
    unsigned long long r;
    asm("mov.b64 %0, {%1, %2};" : "=l"(r) : "f"(x), "f"(y));
    return r;
}
__device__ __forceinline__ void unpack2(unsigned long long v, float& x, float& y) {
    asm("mov.b64 {%0, %1}, %2;" : "=f"(x), "=f"(y) : "l"(v));
}
__device__ __forceinline__ unsigned long long ffma2(unsigned long long a,
                                                    unsigned long long b,
                                                    unsigned long long c) {
    unsigned long long d;
    asm("fma.rn.f32x2 %0, %1, %2, %3;" : "=l"(d) : "l"(a), "l"(b), "l"(c));
    return d;
}
__device__ __forceinline__ unsigned long long fadd2(unsigned long long a,
                                                    unsigned long long b) {
    unsigned long long d;
    asm("add.rn.f32x2 %0, %1, %2;" : "=l"(d) : "l"(a), "l"(b));
    return d;
}
__device__ __forceinline__ float tanh_f(float x) {
    float t;
    asm("tanh.approx.f32 %0, %1;" : "=f"(t) : "f"(x));
    return t;
}
__device__ __forceinline__ float ex2_f(float x) {
    float t;
    asm("ex2.approx.ftz.f32 %0, %1;" : "=f"(t) : "f"(x));
    return t;
}
__device__ __forceinline__ float lg2_f(float x) {
    float t;
    asm("lg2.approx.f32 %0, %1;" : "=f"(t) : "f"(x));
    return t;
}
__device__ __forceinline__ unsigned int packfs(float fhalf, float slog) {
    __nv_bfloat162 h2 = __floats2bfloat162_rn(slog, fhalf);  // .x low = s, .y high = f
    return *reinterpret_cast<unsigned int*>(&h2);
}
__device__ __forceinline__ unsigned long long expandfs(unsigned int w) {
    return pack2(__int_as_float(w & 0xffff0000u), __int_as_float(w << 16));
}

// ---------------- init ----------------
__global__ void init_kernel() {
    int i = blockIdx.x * blockDim.x + threadIdx.x;
    if (i < NN) { d_cnt[i] = 0; d_fill[i] = 0; }
    if (i < NG * NC) d_pool[i] = 0.f;
    if (i < NG) d_gcnt[i] = 0;
    if (i < 2 * NC) d_stats[i] = 0.0;
}

__global__ void hist_kernel(const int* __restrict__ ei, const int* __restrict__ batch) {
    int e = blockIdx.x * blockDim.x + threadIdx.x;
    if (e < NE) atomicAdd(&d_cnt[ei[NE + e]], 1);
    if (e < NN) atomicAdd(&d_gcnt[batch[e]], 1);
}

__global__ void scan_kernel() {
    const int CH = (NN + 1023) / 1024;
    int tid = threadIdx.x;
    int start = tid * CH;
    int end = min(start + CH, NN);
    int s = 0;
    for (int i = start; i < end; i++) s += d_cnt[i];

    __shared__ int warp_sums[32];
    int lane = tid & 31, w = tid >> 5;
    int incl = s;
    #pragma unroll
    for (int o = 1; o < 32; o <<= 1) {
        int t = __shfl_up_sync(0xffffffffu, incl, o);
        if (lane >= o) incl += t;
    }
    if (lane == 31) warp_sums[w] = incl;
    __syncthreads();
    if (w == 0) {
        int v = warp_sums[lane];
        #pragma unroll
        for (int o = 1; o < 32; o <<= 1) {
            int t = __shfl_up_sync(0xffffffffu, v, o);
            if (lane >= o) v += t;
        }
        warp_sums[lane] = v;
    }
    __syncthreads();
    int excl = incl - s + (w > 0 ? warp_sums[w - 1] : 0);
    int run = excl;
    for (int i = start; i < end; i++) { d_off[i] = run; run += d_cnt[i]; }
    if (tid == 1023) d_off[NN] = NE;
}

__global__ void scatter_kernel(const int* __restrict__ ei, const float* __restrict__ ea) {
    int e = blockIdx.x * blockDim.x + threadIdx.x;
    if (e < NE) {
        int d = ei[NE + e];
        int p = atomicAdd(&d_fill[d], 1);
        d_edge[d_off[d] + p] = make_int2(ei[e], __float_as_int(ea[e]));
    }
}

// ---------------- per-warp start node: binary search d_off ----------------
__global__ void wstart_kernel() {
    int w = blockIdx.x * 256 + threadIdx.x;
    if (w >= EWARPS) return;
    int e = w * ECHUNK;
    if (e >= NE) { d_wstart[w] = NN - 1; return; }
    int lo = 0, hi = NN;
    while (hi - lo > 1) {
        int mid = (lo + hi) >> 1;
        if (d_off[mid] <= e) lo = mid; else hi = mid;
    }
    d_wstart[w] = lo;
}

// ---------------- BN prep (reads stats, zeroes them) ----------------
__global__ void bn_prep_kernel(const float* __restrict__ g, const float* __restrict__ beta) {
    int c = threadIdx.x;
    if (c < NC) {
        double mu = d_stats[c] * (1.0 / (double)NN);
        double var = d_stats[NC + c] * (1.0 / (double)NN) - mu * mu;
        float rs = rsqrtf((float)var + EPSBN);
        float sc = g[c] * rs;
        d_bnscale[c] = sc;
        d_bnshift[c] = beta[c] - (float)mu * sc;
        d_stats[c] = 0.0;
        d_stats[NC + c] = 0.0;
    }
}

// ---------------- stats over d_y ----------------
__global__ __launch_bounds__(256) void stats_kernel() {
    __shared__ float ssum[64], ssq[64];
    int tid = threadIdx.x;
    if (tid < 64) { ssum[tid] = 0.f; ssq[tid] = 0.f; }
    __syncthreads();
    int c = tid & 63;
    float ls = 0.f, lq = 0.f;
    const size_t stride = (size_t)SBLOCKS * 256;   // multiple of 64 -> c constant
    for (size_t idx = (size_t)blockIdx.x * 256 + tid; idx < (size_t)NN * NC; idx += stride) {
        float v = d_y[idx];
        ls += v;
        lq = fmaf(v, v, lq);
    }
    atomicAdd(&ssum[c], ls);
    atomicAdd(&ssq[c], lq);
    __syncthreads();
    if (tid < 64) {
        atomicAdd(&d_stats[tid], (double)ssum[tid]);
        atomicAdd(&d_stats[64 + tid], (double)ssq[tid]);
    }
}

// ---------------- input layer ----------------
__global__ __launch_bounds__(256) void input_kernel(const float* __restrict__ x,
                                                    const float* __restrict__ W,
                                                    const float* __restrict__ b) {
    __shared__ float ws[12 * 64];
    __shared__ float xs[64 * 12];
    __shared__ float ssum[64], ssq[64];
    int tid = threadIdx.x;
    int base = blockIdx.x * 64;
    for (int i = tid; i < 12 * 64; i += 256) ws[i] = W[i];
    for (int i = tid; i < 64 * 12; i += 256) {
        int n = i / 12;
        xs[i] = (base + n < NN) ? x[(size_t)(base + n) * 12 + (i % 12)] : 0.f;
    }
    if (tid < 64) { ssum[tid] = 0.f; ssq[tid] = 0.f; }
    __syncthreads();
    int c = tid & 63;
    float bc = b[c];
    float lsum = 0.f, lsq = 0.f;
    #pragma unroll
    for (int p = 0; p < 16; p++) {
        int n = p * 4 + (tid >> 6);
        float acc = bc;
        #pragma unroll
        for (int k = 0; k < 12; k++) acc = fmaf(xs[n * 12 + k], ws[k * 64 + c], acc);
        if (base + n < NN) {
            d_y[(size_t)(base + n) * 64 + c] = acc;
            lsum += acc;
            lsq = fmaf(acc, acc, lsq);
        }
    }
    atomicAdd(&ssum[c], lsum);
    atomicAdd(&ssq[c], lsq);
    __syncthreads();
    if (tid < 64) {
        atomicAdd(&d_stats[tid], (double)ssum[tid]);
        atomicAdd(&d_stats[64 + tid], (double)ssq[tid]);
    }
}

// ---------------- unified GEMM: BN(prev)+res+relu fused, all 4 quadrants ----------------
extern __shared__ float smem_g[];
__global__ __launch_bounds__(256) void gemm_kernel(const float* __restrict__ Wf,
                                                   const float* __restrict__ Ws,
                                                   const float* __restrict__ bfv,
                                                   const float* __restrict__ bsv,
                                                   int residual) {
    float* hsT = smem_g;                                                 // [64][65]
    unsigned long long* wsm2 = (unsigned long long*)(smem_g + 64 * 65);  // [64][128]
    __shared__ float sbn[128];
    int tid = threadIdx.x;
    int nb = blockIdx.x * 64;

    if (tid < 64) { sbn[tid] = d_bnscale[tid]; sbn[64 + tid] = d_bnshift[tid]; }
    __syncthreads();

    #pragma unroll
    for (int m = 0; m < 32; m++) {
        int lin = m * 256 + tid;
        int k = lin >> 7, ch = lin & 127;
        int row = ((ch >> 6) << 6) + k;
        int c = ch & 63;
        wsm2[lin] = pack2(Wf[row * 64 + c], Ws[row * 64 + c]);
    }
    #pragma unroll
    for (int m = 0; m < 16; m++) {
        int lin = m * 256 + tid;
        int a = lin >> 6, c = lin & 63;
        int n = nb + a;
        float v = 0.f;
        if (n < NN) {
            size_t g = (size_t)n * 64 + c;
            v = fmaf(d_y[g], sbn[c], sbn[64 + c]);
            if (residual) v += d_h[g];
            v = fmaxf(v, 0.f);
            d_h[g] = v;
            d_y[g] = 0.f;
        }
        hsT[c * 65 + a] = v;
    }
    __syncthreads();

    int ty = tid >> 5, tx = tid & 31;
    int chbase = ((tx & 15) << 2) + ((tx >> 4) << 6);
    unsigned long long acc[8][4];
    #pragma unroll
    for (int j = 0; j < 8; j++)
        #pragma unroll
        for (int q = 0; q < 4; q++) acc[j][q] = 0ull;

    #pragma unroll 4
    for (int k = 0; k < 64; k++) {
        const unsigned long long* wr = &wsm2[k * 128 + chbase];
        ulonglong2 bq0 = *(const ulonglong2*)(wr);
        ulonglong2 bq1 = *(const ulonglong2*)(wr + 2);
        const float* hr = &hsT[k * 65 + ty * 8];
        #pragma unroll
        for (int j = 0; j < 8; j++) {
            float a = hr[j];
            unsigned long long aa = pack2(a, a);
            acc[j][0] = ffma2(aa, bq0.x, acc[j][0]);
            acc[j][1] = ffma2(aa, bq0.y, acc[j][1]);
            acc[j][2] = ffma2(aa, bq1.x, acc[j][2]);
            acc[j][3] = ffma2(aa, bq1.y, acc[j][3]);
        }
    }

    bool aSide = (tx < 16);
    int ch0 = (tx & 15) * 4;
    float bfr[4], bsr[4];
    if (aSide) {
        #pragma unroll
        for (int q = 0; q < 4; q++) {
            bfr[q] = 0.5f * bfv[ch0 + q];          // pre-halved for tanh fold
            bsr[q] = LOG2E * bsv[ch0 + q];
        }
    }
    unsigned long long* A2 = (unsigned long long*)d_A;
    #pragma unroll
    for (int j = 0; j < 8; j++) {
        int n = nb + ty * 8 + j;
        if (n >= NN) continue;
        #pragma unroll
        for (int q = 0; q < 4; q++) {
            float f, s;
            unpack2(acc[j][q], f, s);
            if (aSide) {
                float fa = fmaf(0.5f, f, bfr[q]);
                float sa = fmaf(LOG2E, s, bsr[q]);
                A2[(size_t)n * 64 + ch0 + q] = pack2(fa, sa);
            } else {
                d_Bb[(size_t)n * 64 + ch0 + q] = packfs(0.5f * f, LOG2E * s);
            }
        }
    }
}

// ---------------- edge pass: warp-chunk CSR walk, 2-deep decoupled prefetch ----------------
__global__ __launch_bounds__(128) void edge_kernel(const float* __restrict__ Wf,
                                                   const float* __restrict__ Ws) {
    int lane = threadIdx.x & 31;
    int gw = blockIdx.x * 4 + (threadIdx.x >> 5);
    int e = gw * ECHUNK;
    int e1 = min(e + ECHUNK, NE);
    if (e >= e1) return;
    int c0 = lane, c1 = lane + 32;
    unsigned long long wfs0 = pack2(0.5f * Wf[128 * 64 + c0], LOG2E * Ws[128 * 64 + c0]);
    unsigned long long wfs1 = pack2(0.5f * Wf[128 * 64 + c1], LOG2E * Ws[128 * 64 + c1]);

    int cur = d_wstart[gw];
    int nend = d_off[cur + 1];                 // > e by construction

    const unsigned long long* A2 = (const unsigned long long*)d_A;
    unsigned long long afs0 = A2[(size_t)cur * 64 + c0];
    unsigned long long afs1 = A2[(size_t)cur * 64 + c1];

    // pipeline state: current edge (record + B data), next edge record
    int2 m_cur = d_edge[e];
    unsigned int w0_cur = d_Bb[(size_t)m_cur.x * 64 + c0];
    unsigned int w1_cur = d_Bb[(size_t)m_cur.x * 64 + c1];
    int2 m_nxt = d_edge[min(e + 1, e1 - 1)];

    unsigned long long acc0 = 0ull, acc1 = 0ull;   // (sum t*l, sum l)

    while (true) {
        // prefetch: record for e+2 (independent), B-gather for e+1 (record ready)
        int2 m_n2 = d_edge[min(e + 2, e1 - 1)];
        unsigned int w0_n = d_Bb[(size_t)m_nxt.x * 64 + c0];
        unsigned int w1_n = d_Bb[(size_t)m_nxt.x * 64 + c1];

        // compute on current edge
        float ea = __int_as_float(m_cur.y);
        unsigned long long ea2 = pack2(ea, ea);
        unsigned long long t0p = fadd2(ffma2(ea2, wfs0, afs0), expandfs(w0_cur));
        float tf0, ts0; unpack2(t0p, tf0, ts0);
        float th0 = tanh_f(tf0);
        float l0 = lg2_f(1.f + ex2_f(ts0));
        acc0 = ffma2(pack2(th0, 1.f), pack2(l0, l0), acc0);

        unsigned long long t1p = fadd2(ffma2(ea2, wfs1, afs1), expandfs(w1_cur));
        float tf1, ts1; unpack2(t1p, tf1, ts1);
        float th1 = tanh_f(tf1);
        float l1 = lg2_f(1.f + ex2_f(ts1));
        acc1 = ffma2(pack2(th1, 1.f), pack2(l1, l1), acc1);

        e++;
        if (e == nend || e == e1) {
            float aT0, aL0, aT1, aL1;
            unpack2(acc0, aT0, aL0);
            unpack2(acc1, aT1, aL1);
            atomicAdd(&d_y[(size_t)cur * 64 + c0], HALF_LN2 * (aT0 + aL0));
            atomicAdd(&d_y[(size_t)cur * 64 + c1], HALF_LN2 * (aT1 + aL1));
            if (e == e1) break;
            acc0 = 0ull; acc1 = 0ull;
            do { cur++; nend = d_off[cur + 1]; } while (nend <= e);
            afs0 = A2[(size_t)cur * 64 + c0];
            afs1 = A2[(size_t)cur * 64 + c1];
        }
        m_cur = m_nxt; w0_cur = w0_n; w1_cur = w1_n; m_nxt = m_n2;
    }
}

// ---------------- BN apply + pooled (last layer, batch sorted) ----------------
__global__ __launch_bounds__(1024) void bn_pool_kernel(const int* __restrict__ batch) {
    __shared__ float psum[64];
    __shared__ int sg[2];
    int tid = threadIdx.x;
    int idx = blockIdx.x * 1024 + tid;
    int node = idx >> 6;
    int c = idx & 63;
    float v = fmaf(d_y[idx], d_bnscale[c], d_bnshift[c]) + d_h[idx];
    int g = batch[node];
    if (tid == 0)    sg[0] = g;
    if (tid == 1023) sg[1] = g;
    __syncthreads();
    int g0 = sg[0], g1 = sg[1];
    for (int gg = g0; gg <= g1; gg++) {
        if (tid < 64) psum[tid] = 0.f;
        __syncthreads();
        if (g == gg) atomicAdd(&psum[c], v);
        __syncthreads();
        if (tid < 64 && psum[tid] != 0.f) atomicAdd(&d_pool[gg * 64 + tid], psum[tid]);
        __syncthreads();
    }
}

// ---------------- final MLP ----------------
__global__ void mlp_kernel(const float* __restrict__ W1, const float* __restrict__ b1,
                           const float* __restrict__ W2, const float* __restrict__ b2,
                           float* __restrict__ out) {
    __shared__ float p[64];
    __shared__ float h1[32];
    int g = blockIdx.x;
    int tid = threadIdx.x;
    float inv = 1.f / fmaxf((float)d_gcnt[g], 1.f);
    p[tid] = d_pool[g * 64 + tid] * inv;
    __syncthreads();
    if (tid < 32) {
        float a = b1[tid];
        #pragma unroll
        for (int k = 0; k < 64; k++) a = fmaf(p[k], W1[k * 32 + tid], a);
        h1[tid] = fmaxf(a, 0.f);
    }
    __syncthreads();
    if (tid < 32) {
        float v = h1[tid] * W2[tid];
        #pragma unroll
        for (int o = 16; o > 0; o >>= 1) v += __shfl_down_sync(0xffffffffu, v, o);
        if (tid == 0) out[g] = v + b2[0];
    }
}

// ---------------- launcher ----------------
extern "C" void kernel_launch(void* const* d_in, const int* in_sizes, int n_in,
                              void* d_out, int out_size) {
    const float* x     = (const float*)d_in[0];
    const int*   ei    = (const int*)d_in[1];
    const float* ea    = (const float*)d_in[2];
    const int*   batch = (const int*)d_in[3];
    const float* W_in  = (const float*)d_in[4];
    const float* b_in  = (const float*)d_in[5];
    const float* g0    = (const float*)d_in[6];
    const float* beta0 = (const float*)d_in[7];
    const float* Wf[3] = {(const float*)d_in[8],  (const float*)d_in[14], (const float*)d_in[20]};
    const float* bf[3] = {(const float*)d_in[9],  (const float*)d_in[15], (const float*)d_in[21]};
    const float* Ws[3] = {(const float*)d_in[10], (const float*)d_in[16], (const float*)d_in[22]};
    const float* bs[3] = {(const float*)d_in[11], (const float*)d_in[17], (const float*)d_in[23]};
    const float* gg[3] = {(const float*)d_in[12], (const float*)d_in[18], (const float*)d_in[24]};
    const float* bb[3] = {(const float*)d_in[13], (const float*)d_in[19], (const float*)d_in[25]};
    const float* W1 = (const float*)d_in[26];
    const float* b1 = (const float*)d_in[27];
    const float* W2 = (const float*)d_in[28];
    const float* b2 = (const float*)d_in[29];
    float* out = (float*)d_out;

    const int GEMM_SMEM = 64 * 65 * 4 + 64 * 128 * 8;   // 82176 bytes
    cudaFuncSetAttribute(gemm_kernel, cudaFuncAttributeMaxDynamicSharedMemorySize, GEMM_SMEM);

    init_kernel<<<(NN + 255) / 256, 256>>>();
    hist_kernel<<<(NE + 255) / 256, 256>>>(ei, batch);
    scan_kernel<<<1, 1024>>>();
    scatter_kernel<<<(NE + 255) / 256, 256>>>(ei, ea);
    wstart_kernel<<<(EWARPS + 255) / 256, 256>>>();

    input_kernel<<<(NN + 63) / 64, 256>>>(x, W_in, b_in);
    bn_prep_kernel<<<1, 64>>>(g0, beta0);

    for (int l = 0; l < 3; l++) {
        gemm_kernel<<<(NN + 63) / 64, 256, GEMM_SMEM>>>(Wf[l], Ws[l], bf[l], bs[l],
                                                        (l == 0) ? 0 : 1);
        edge_kernel<<<EWARPS / 4, 128>>>(Wf[l], Ws[l]);
        stats_kernel<<<SBLOCKS, 256>>>();
        bn_prep_kernel<<<1, 64>>>(gg[l], bb[l]);
    }

    bn_pool_kernel<<<(NN * NC + 1023) / 1024, 1024>>>(batch);
    mlp_kernel<<<NG, 64>>>(W1, b1, W2, b2, out);
}